// round 11
// baseline (speedup 1.0000x reference)
#include <cuda_runtime.h>
#include <cuda_bf16.h>

// Wav2Frames: out[b, c, f] = x[b, f*WINSTEP + c]
// x: (32, 1, 480000) fp32 -> out: (32, 400, 2998) fp32
//
// R11 = R10 with EXACT slot packing: 888 jobs = 3 rounds x 296 slots
// (2 CTAs/SM x 148 SMs), 100% slot fill vs R10's 97.3%.
//   batches  0..23: 28 tiles of F_TILE=108  (24*28 = 672 jobs)
//   batches 24..31: 27 tiles of F_TILE=112  ( 8*27 = 216 jobs)
// All mechanics unchanged from R10 (confirmed best): float4 LDG fill,
// smem skew j+(j>>5) (conflict-free STS / 2-way LDS), per-row sector
// shift s(c)=(2c)&7 (confirmed RMW win), float2 frame-pair stores,
// 1024 threads, 2 CTAs/SM.

#define B        32
#define T        480000
#define WINLEN   400
#define WINSTEP  160
#define NFRAMES  2998
#define FT_A     108
#define NT_A     28
#define NB_A     24                                    // batches with type A
#define FT_B     112
#define NT_B     27
#define JOBS_A   (NB_A * NT_A)                         // 672
#define NJOBS    888                                   // 672 + 8*27 = 3*296
#define SPAN_MAX (160 * FT_B + 1200)                   // 19120 (ft=112)
#define SM_SZ    (SPAN_MAX + SPAN_MAX / 32 + 4)        // 19721 floats (~78.9 KB)
#define THREADS  1024

__global__ __launch_bounds__(THREADS, 2)
void wav2frames_kernel(const float* __restrict__ x, float* __restrict__ out) {
    extern __shared__ float sm[];

    // ---- job decode: mixed tile sizes for exact 888-job packing ----
    const int job = blockIdx.x;
    int b, tile, ft;
    if (job < JOBS_A) {
        b    = job / NT_A;
        tile = job - b * NT_A;
        ft   = FT_A;
    } else {
        const int j2 = job - JOBS_A;
        const int bb = j2 / NT_B;
        b    = NB_A + bb;
        tile = j2 - bb * NT_B;
        ft   = FT_B;
    }

    const int tid  = threadIdx.x;
    const int lane = tid & 31;
    const int w    = tid >> 5;                         // 32 warps

    const int f0 = tile * ft;                          // even
    const int x0 = f0 * WINSTEP;

    // ---- vectorized coalesced fill: gmem float4 -> skewed smem ----
    const float* __restrict__ xb = x + (size_t)b * T + x0;
    const int spanlen = 160 * ft + 1200;               // (ft-1)*160+400+960
    const int span    = (x0 + spanlen <= T) ? spanlen : (T - x0);
    const int span4   = span >> 2;                     // span multiple of 4
    const float4* __restrict__ xb4 = reinterpret_cast<const float4*>(xb);

    for (int i4 = tid; i4 < span4; i4 += THREADS) {    // ~5 iterations
        const float4 v = xb4[i4];
        const int i = i4 << 2;
        const int p = i + (i >> 5);                    // skew: j + (j>>5)
        sm[p + 0] = v.x;
        sm[p + 1] = v.y;
        sm[p + 2] = v.z;
        sm[p + 3] = v.w;
    }
    __syncthreads();

    float* __restrict__ outb = out + (size_t)b * WINLEN * NFRAMES;

    // ---- main store: ft/2 frame pairs x 16 c-groups, sector-aligned ----
    const int q      = w & 1;
    const int cg     = w >> 1;                         // 0..15
    const int fp_idx = lane + 32 * q;                  // 0..63 (tail idle)
    const int fbase  = f0 + 2 * fp_idx;                // even
    const int jbase  = 2 * fp_idx * WINSTEP;           // 320 * fp_idx

    if (fp_idx < (ft >> 1)) {
        #pragma unroll 5
        for (int c = cg; c < WINLEN; c += 16) {        // 25 iterations
            const int s = (2 * c) & 7;                 // 0,2,4,6 (even)
            const int f = fbase + s;
            if (f <= NFRAMES - 2) {
                const int j0 = jbase + s * WINSTEP + c;
                const int j1 = j0 + WINSTEP;
                float2 v;
                v.x = sm[j0 + (j0 >> 5)];
                v.y = sm[j1 + (j1 >> 5)];
                *reinterpret_cast<float2*>(outb + (size_t)c * NFRAMES + f) = v;
            }
        }
    }

    // ---- head: tile 0 of each batch writes frames [0, s(c)) per row ----
    if (tile == 0) {
        for (int idx = tid; idx < WINLEN * 3; idx += THREADS) {
            const int c = idx / 3;
            const int m = idx - 3 * c;                 // pair slot 0..2
            const int s = (2 * c) & 7;
            if (2 * m < s) {
                const int fh = 2 * m;
                const int j0 = fh * WINSTEP + c;
                const int j1 = j0 + WINSTEP;
                float2 v;
                v.x = sm[j0 + (j0 >> 5)];
                v.y = sm[j1 + (j1 >> 5)];
                *reinterpret_cast<float2*>(outb + (size_t)c * NFRAMES + fh) = v;
            }
        }
    }
}

extern "C" void kernel_launch(void* const* d_in, const int* in_sizes, int n_in,
                              void* d_out, int out_size) {
    const float* x = (const float*)d_in[0];            // (32, 1, 480000) fp32
    // d_in[1] = W (identity, unused), d_in[2] = winstep (fixed 160, unused)
    float* out = (float*)d_out;                        // (32, 400, 2998) fp32

    static bool configured = false;
    if (!configured) {
        cudaFuncSetAttribute(wav2frames_kernel,
                             cudaFuncAttributeMaxDynamicSharedMemorySize,
                             SM_SZ * (int)sizeof(float));
        configured = true;
    }

    wav2frames_kernel<<<NJOBS, THREADS, SM_SZ * sizeof(float)>>>(x, out);
}